// round 5
// baseline (speedup 1.0000x reference)
#include <cuda_runtime.h>
#include <cstdint>

// EngramMemory, scatter-by-bucket formulation.
// tokens: (4,4096) int64 (or int32; auto-detected)   tables: (8,2048,256) f32
// out: (4,4096,2048) f32
//
// hash per (order oi in {2,3}, head hd): seed = 1337+97*order+17*hd
//   h = 0; for tok in window (oldest->newest, zero-padded): h = (h*1000003+tok+seed) mod 2048
// out[b,s, oh*256 : +256] = tables[oh][h],  oh = oi*4+hd
//
// Only 16384 distinct (oh,bucket) rows vs 131072 gathers (8x redundancy).
// Build an inverted index, then each warp reads its row ONCE and streams it
// to all positions that hashed to it. Cuts L2 read traffic 134MB -> 16MB.

#define B_      4
#define S_      4096
#define NBUCK   2048u
#define PRIME_  1000003u
#define NTOK    (B_ * S_)          // 16384
#define NROWS   (8 * 2048)         // 16384 (oh,bucket) pairs
#define CAP     256

__device__ int            g_cnt[NROWS];
__device__ unsigned short g_list[NROWS * CAP];   // 8 MB static scratch

__global__ void k_zero()
{
    const int i = blockIdx.x * blockDim.x + threadIdx.x;
    if (i < NROWS) g_cnt[i] = 0;
}

__global__ __launch_bounds__(256) void k_build(
    const unsigned* __restrict__ tok32,
    const float4* __restrict__ tables,
    float4* __restrict__ out)
{
    const int bs   = blockIdx.x * blockDim.x + threadIdx.x;   // 0..16383
    const int lane = threadIdx.x & 31;
    const int s = bs & (S_ - 1);
    const int b = bs >> 12;

    // dtype probe: 8 fixed odd words within the first 16384 words (safe for both
    // dtypes). int64 tokens < 2^31 => odd (high) words are all 0.
    unsigned probe = 0u;
    if (lane < 8) probe = tok32[(lane * (NTOK / 8)) | 1];
    const bool is64 = __all_sync(0xFFFFFFFFu, probe == 0u);

    // 3-token window, zero-padded
    unsigned t0 = 0u, t1 = 0u, t2;
    {
        const int base = b * S_ + s;
        if (is64) {
            t2 = tok32[2 * base];
            if (s >= 1) t1 = tok32[2 * (base - 1)];
            if (s >= 2) t0 = tok32[2 * (base - 2)];
        } else {
            t2 = tok32[base];
            if (s >= 1) t1 = tok32[base - 1];
            if (s >= 2) t0 = tok32[base - 2];
        }
    }

    #pragma unroll
    for (int oh = 0; oh < 8; oh++) {
        const int head  = oh & 3;
        const int order = 2 + (oh >> 2);
        const unsigned seed = 1337u + 97u * (unsigned)order + 17u * (unsigned)head;
        unsigned h = 0;
        if (order == 3) h = (h * PRIME_ + t0 + seed) & (NBUCK - 1u);
        h = (h * PRIME_ + t1 + seed) & (NBUCK - 1u);
        h = (h * PRIME_ + t2 + seed) & (NBUCK - 1u);

        const int row  = oh * (int)NBUCK + (int)h;
        const int slot = atomicAdd(&g_cnt[row], 1);
        if (slot < CAP) {
            g_list[row * CAP + slot] = (unsigned short)bs;
        } else {
            // overflow fallback (astronomically unlikely for random tokens):
            // copy the row directly for this (bs,oh)
            const float4* src = tables + (size_t)row * 64;
            float4* dst = out + (size_t)bs * 512 + (size_t)oh * 64;
            #pragma unroll 8
            for (int j = 0; j < 64; j++) dst[j] = src[j];
        }
    }
}

__global__ __launch_bounds__(256) void k_scatter(
    const float4* __restrict__ tables,
    float4* __restrict__ out)
{
    // one warp per (oh,bucket) row
    const int w    = (blockIdx.x * blockDim.x + threadIdx.x) >> 5;  // 0..16383
    const int lane = threadIdx.x & 31;
    const int oh   = w >> 11;

    int n = g_cnt[w];
    if (n > CAP) n = CAP;
    if (n == 0) return;

    // load the 1KB table row once (2 x float4 per lane)
    const float4* src = tables + (size_t)w * 64;
    const float4 r0 = src[lane];
    const float4 r1 = src[lane + 32];

    const unsigned short* lst = g_list + (size_t)w * CAP;

    for (int base = 0; base < n; base += 32) {
        const int m = min(32, n - base);
        unsigned bs_l = 0;
        if (lane < m) bs_l = lst[base + lane];
        #pragma unroll 4
        for (int i = 0; i < m; i++) {
            const unsigned bs = __shfl_sync(0xFFFFFFFFu, bs_l, i);
            float4* dst = out + (size_t)bs * 512 + (size_t)oh * 64;
            __stcs(dst + lane,      r0);
            __stcs(dst + lane + 32, r1);
        }
    }
}

extern "C" void kernel_launch(void* const* d_in, const int* in_sizes, int n_in,
                              void* d_out, int out_size)
{
    // assign by element count: tokens=16384, tables=4194304
    const void* tokens_p = d_in[0];
    const void* tables_p = d_in[1];
    if (n_in >= 2 && in_sizes[0] > in_sizes[1]) {
        tokens_p = d_in[1];
        tables_p = d_in[0];
    }

    const unsigned* tok32  = (const unsigned*)tokens_p;
    const float4*   tables = (const float4*)tables_p;
    float4*         out    = (float4*)d_out;

    k_zero<<<(NROWS + 1023) / 1024, 1024>>>();
    k_build<<<NTOK / 256, 256>>>(tok32, tables, out);
    k_scatter<<<(NROWS * 32) / 256, 256>>>(tables, out);
}